// round 3
// baseline (speedup 1.0000x reference)
#include <cuda_runtime.h>

// VQ-VAE vector quantizer for GB300.
// latents: [B=32, D=64, H=64, W=64] fp32, emb_weight: [K=512, D=64] fp32.
// Out: q_st transposed back to [B, D, H, W] (8388608 floats) + vq_loss scalar.
//
// Precision strategy: replicate the reference fp32 rounding chain exactly:
//   sumw_k = sum_d fl(w*w)        (unfused mul+add, ascending d)
//   sumf   = sum_d fl(f*f)        (unfused mul+add, ascending d)
//   s_k    = fma-chain over d (ascending, single accumulator)
//   dist   = fl( fl(sumf + sumw_k) - fl(2*s_k) )
//   argmin: strict <, ascending k (first-index tie-break, matches jnp.argmin)
//   q_st   = fl( f + fl(q - f) )
// Losses accumulated in double (tolerance 1e-3 on the scalar is generous).

#define KCODES 512
#define DDIM   64
#define HW     4096           // H*W
#define NPIX   131072         // B*H*W
#define BLOCK  256
#define PPT    2              // pixels per thread (2 independent FMA chains)
#define NELEM  8388608        // B*D*H*W

__device__ double g_loss_sum;
__device__ float  g_sumw[KCODES];

__global__ void vq_prep_kernel(const float* __restrict__ w) {
    int k = blockIdx.x * blockDim.x + threadIdx.x;
    if (k == 0) g_loss_sum = 0.0;
    if (k < KCODES) {
        const float* wr = w + k * DDIM;
        float acc = 0.0f;
#pragma unroll
        for (int d = 0; d < DDIM; ++d)
            acc = __fadd_rn(acc, __fmul_rn(wr[d], wr[d]));
        g_sumw[k] = acc;
    }
}

__global__ void __launch_bounds__(BLOCK) vq_main_kernel(
    const float* __restrict__ lat,
    const float* __restrict__ w,
    float* __restrict__ out)
{
    extern __shared__ char smem_raw[];
    float4* sw    = reinterpret_cast<float4*>(smem_raw);                   // 512*64 floats
    float*  ssumw = reinterpret_cast<float*>(smem_raw + KCODES * DDIM * 4);// 512 floats
    double* sred  = reinterpret_cast<double*>(smem_raw + KCODES * DDIM * 4 + KCODES * 4);

    // Cooperative codebook load (128 KB, stays resident for the whole block)
    const float4* wv4 = reinterpret_cast<const float4*>(w);
#pragma unroll 4
    for (int i = threadIdx.x; i < KCODES * DDIM / 4; i += BLOCK)
        sw[i] = wv4[i];
    for (int i = threadIdx.x; i < KCODES; i += BLOCK)
        ssumw[i] = g_sumw[i];
    __syncthreads();

    const int base = blockIdx.x * (BLOCK * PPT) + threadIdx.x;

    float f[PPT][DDIM];
    float sumf[PPT];
    int   n[PPT];

#pragma unroll
    for (int p = 0; p < PPT; ++p) {
        n[p] = base + p * BLOCK;
        int b  = n[p] >> 12;
        int hw = n[p] & (HW - 1);
        const float* lp = lat + (size_t)b * (DDIM * HW) + hw;
        float acc = 0.0f;
#pragma unroll
        for (int d = 0; d < DDIM; ++d) {
            float v = lp[(size_t)d * HW];
            f[p][d] = v;
            acc = __fadd_rn(acc, __fmul_rn(v, v));  // unfused, ascending d
        }
        sumf[p] = acc;
    }

    float best[PPT];
    int   bi[PPT];
#pragma unroll
    for (int p = 0; p < PPT; ++p) { best[p] = 3.4e38f; bi[p] = 0; }

#pragma unroll 2
    for (int k = 0; k < KCODES; ++k) {
        float swk = ssumw[k];           // scalar LDS issues early, under FMA block
        float s[PPT];
#pragma unroll
        for (int p = 0; p < PPT; ++p) s[p] = 0.0f;
#pragma unroll
        for (int j = 0; j < DDIM / 4; ++j) {
            float4 wv = sw[k * (DDIM / 4) + j];   // warp-uniform -> LDS broadcast
#pragma unroll
            for (int p = 0; p < PPT; ++p) {
                s[p] = __fmaf_rn(f[p][4 * j + 0], wv.x, s[p]);
                s[p] = __fmaf_rn(f[p][4 * j + 1], wv.y, s[p]);
                s[p] = __fmaf_rn(f[p][4 * j + 2], wv.z, s[p]);
                s[p] = __fmaf_rn(f[p][4 * j + 3], wv.w, s[p]);
            }
        }
#pragma unroll
        for (int p = 0; p < PPT; ++p) {
            float dist = __fsub_rn(__fadd_rn(sumf[p], swk), __fmul_rn(2.0f, s[p]));
            if (dist < best[p]) { best[p] = dist; bi[p] = k; }
        }
    }

    // Gather winning code, write straight-through output, accumulate loss
    double lloss = 0.0;
#pragma unroll
    for (int p = 0; p < PPT; ++p) {
        int b  = n[p] >> 12;
        int hw = n[p] & (HW - 1);
        float* op = out + (size_t)b * (DDIM * HW) + hw;
        const float* q = reinterpret_cast<const float*>(&sw[bi[p] * (DDIM / 4)]);
#pragma unroll
        for (int d = 0; d < DDIM; ++d) {
            float qd   = q[d];
            float fd   = f[p][d];
            float diff = __fsub_rn(qd, fd);
            op[(size_t)d * HW] = __fadd_rn(fd, diff);   // lat + (q - lat), both rounded
            lloss += (double)diff * (double)diff;
        }
    }

    // Block reduction of loss -> one atomicAdd per block
    unsigned mask = 0xFFFFFFFFu;
#pragma unroll
    for (int off = 16; off > 0; off >>= 1)
        lloss += __shfl_down_sync(mask, lloss, off);
    int lane = threadIdx.x & 31;
    int wid  = threadIdx.x >> 5;
    if (lane == 0) sred[wid] = lloss;
    __syncthreads();
    if (threadIdx.x == 0) {
        double t = 0.0;
#pragma unroll
        for (int i = 0; i < BLOCK / 32; ++i) t += sred[i];
        atomicAdd(&g_loss_sum, t);
    }
}

__global__ void vq_final_kernel(float* __restrict__ out, int loss_idx) {
    if (threadIdx.x == 0 && blockIdx.x == 0) {
        double mean = g_loss_sum / (double)NELEM;
        float m = (float)mean;
        // commitment*0.25 + embedding, both numerically equal to mean
        out[loss_idx] = __fadd_rn(__fmul_rn(m, 0.25f), m);
    }
}

extern "C" void kernel_launch(void* const* d_in, const int* in_sizes, int n_in,
                              void* d_out, int out_size) {
    const float* lat = (const float*)d_in[0];
    const float* w   = (const float*)d_in[1];
    float* out = (float*)d_out;

    const int smem_bytes = KCODES * DDIM * 4 + KCODES * 4 + (BLOCK / 32) * 8;
    cudaFuncSetAttribute(vq_main_kernel,
                         cudaFuncAttributeMaxDynamicSharedMemorySize, smem_bytes);

    vq_prep_kernel<<<1, KCODES>>>(w);

    const int pixels_per_block = BLOCK * PPT;
    const int grid = NPIX / pixels_per_block;   // 256 blocks
    vq_main_kernel<<<grid, BLOCK, smem_bytes>>>(lat, w, out);

    vq_final_kernel<<<1, 32>>>(out, out_size - 1);
}